// round 1
// baseline (speedup 1.0000x reference)
#include <cuda_runtime.h>

#define Bb 2
#define Nn 2048
#define Dd 1024
#define Hh 16
#define HD 64

// Scratch (static device arrays -- no allocation allowed)
__device__ float g_qt[Bb*Hh*HD*Nn];   // [B,H,hd,N]  (transposed for attention)
__device__ float g_kt[Bb*Hh*HD*Nn];   // [B,H,hd,N]
__device__ float g_v [Bb*Hh*Nn*HD];   // [B,H,N,hd]
__device__ float g_attn[Bb*Nn*Dd];    // [B*N, D]

// ---------------------------------------------------------------------------
// SGEMM 128x128x16, 256 threads, 8x8 microtile (split-tile fragments).
// EPI==0: C = A@B + bias scattered into q/k/v scratch (qkv projection)
// EPI==1: C = g_attn@B + bias written to Cout (output projection)
// ---------------------------------------------------------------------------
template<int NCOLS, int EPI>
__global__ void __launch_bounds__(256)
sgemm_kernel(const float* __restrict__ A, const float* __restrict__ B,
             const float* __restrict__ bias, float* __restrict__ Cout)
{
    __shared__ float As[16][128];
    __shared__ float Bs[16][132];

    const int t  = threadIdx.x;
    const int tx = t & 15;
    const int ty = t >> 4;
    const int m0 = blockIdx.y * 128;
    const int n0 = blockIdx.x * 128;

    const float* Ap = (EPI == 1) ? g_attn : A;

    float acc[8][8];
    #pragma unroll
    for (int i = 0; i < 8; i++)
        #pragma unroll
        for (int j = 0; j < 8; j++) acc[i][j] = 0.f;

    for (int k0 = 0; k0 < 1024; k0 += 16) {
        // A tile: 128x16, stored transposed into As[k][m]
        #pragma unroll
        for (int s = 0; s < 2; s++) {
            int f   = t + s * 256;       // 0..511 float4s
            int row = f >> 2;            // 0..127
            int c4  = (f & 3) * 4;       // 0,4,8,12
            float4 v = *(const float4*)(Ap + (size_t)(m0 + row) * 1024 + k0 + c4);
            As[c4 + 0][row] = v.x; As[c4 + 1][row] = v.y;
            As[c4 + 2][row] = v.z; As[c4 + 3][row] = v.w;
        }
        // B tile: 16x128
        #pragma unroll
        for (int s = 0; s < 2; s++) {
            int f   = t + s * 256;
            int row = f >> 5;            // 0..15
            int c4  = (f & 31) * 4;      // 0..124
            *(float4*)&Bs[row][c4] =
                *(const float4*)(B + (size_t)(k0 + row) * NCOLS + n0 + c4);
        }
        __syncthreads();

        #pragma unroll
        for (int k = 0; k < 16; k++) {
            float4 a0 = *(const float4*)&As[k][ty * 4];
            float4 a1 = *(const float4*)&As[k][64 + ty * 4];
            float4 b0 = *(const float4*)&Bs[k][tx * 4];
            float4 b1 = *(const float4*)&Bs[k][64 + tx * 4];
            float ar[8] = {a0.x, a0.y, a0.z, a0.w, a1.x, a1.y, a1.z, a1.w};
            float br[8] = {b0.x, b0.y, b0.z, b0.w, b1.x, b1.y, b1.z, b1.w};
            #pragma unroll
            for (int i = 0; i < 8; i++)
                #pragma unroll
                for (int j = 0; j < 8; j++)
                    acc[i][j] += ar[i] * br[j];
        }
        __syncthreads();
    }

    // Epilogue
    #pragma unroll
    for (int i = 0; i < 8; i++) {
        int r = m0 + ((i < 4) ? (ty * 4 + i) : (64 + ty * 4 + i - 4));
        #pragma unroll
        for (int j = 0; j < 8; j++) {
            int c = n0 + ((j < 4) ? (tx * 4 + j) : (64 + tx * 4 + j - 4));
            float v = acc[i][j] + __ldg(bias + c);
            if (EPI == 0) {
                int tt  = c >> 10;         // 0=q,1=k,2=v
                int rem = c & 1023;
                int h   = rem >> 6;
                int d   = rem & 63;
                int b   = r >> 11;
                int n   = r & 2047;
                int bh  = b * Hh + h;
                if (tt == 0)      g_qt[(((size_t)bh * HD + d) << 11) + n] = v;
                else if (tt == 1) g_kt[(((size_t)bh * HD + d) << 11) + n] = v;
                else              g_v [(((size_t)bh * Nn + n) << 6)  + d] = v;
            } else {
                Cout[(size_t)r * 1024 + c] = v;
            }
        }
    }
}

// ---------------------------------------------------------------------------
// Flash-style attention: 64-query tile per block, stream 64-key tiles.
// Online softmax, fp32. 256 threads, 4x4 microtiles.
// smem: Qt (Q transposed [d][i]), KPt (K transposed [d][j], reused for P^T),
//       Vs ([j][d]). Exactly 48KB static.
// ---------------------------------------------------------------------------
__global__ void __launch_bounds__(256)
attn_kernel(const float* __restrict__ bias)
{
    __shared__ float Qt [64][64];
    __shared__ float KPt[64][64];
    __shared__ float Vs [64][64];

    const int t  = threadIdx.x;
    const int tx = t & 15;
    const int ty = t >> 4;
    const int bh = blockIdx.y;          // b*H + h
    const int b  = bh >> 4;
    const int h  = bh & 15;
    const int q0 = blockIdx.x * 64;

    const float* qtp = g_qt + (size_t)bh * HD * Nn;
    const float* ktp = g_kt + (size_t)bh * HD * Nn;
    const float* vp  = g_v  + (size_t)bh * Nn * HD;
    const float* bp  = bias + b * Nn;

    // Load Q tile (transposed layout in gmem already): Qt[d][i]
    #pragma unroll
    for (int p = 0; p < 4; p++) {
        int d = p * 16 + ty;
        *(float4*)&Qt[d][tx * 4] =
            *(const float4*)(qtp + (size_t)d * Nn + q0 + tx * 4);
    }

    float o[4][4];
    float m[4], l[4];
    #pragma unroll
    for (int i = 0; i < 4; i++) {
        m[i] = -1e30f; l[i] = 0.f;
        #pragma unroll
        for (int d = 0; d < 4; d++) o[i][d] = 0.f;
    }

    const int i0 = ty * 4;
    const int j0 = tx * 4;

    for (int k0 = 0; k0 < Nn; k0 += 64) {
        __syncthreads();   // prev O-stage reads done (also covers Q-load on iter 0)

        // Load K tile transposed (KPt[d][j]) and V tile (Vs[j][d])
        #pragma unroll
        for (int p = 0; p < 4; p++) {
            int rr = p * 16 + ty;
            *(float4*)&KPt[rr][tx * 4] =
                *(const float4*)(ktp + (size_t)rr * Nn + k0 + tx * 4);
            *(float4*)&Vs[rr][tx * 4] =
                *(const float4*)(vp + (size_t)(k0 + rr) * HD + tx * 4);
        }
        __syncthreads();

        // S = (Q.K^T)/8 + bias
        float s[4][4];
        #pragma unroll
        for (int i = 0; i < 4; i++)
            #pragma unroll
            for (int j = 0; j < 4; j++) s[i][j] = 0.f;

        #pragma unroll
        for (int d = 0; d < 64; d++) {
            float4 qv = *(const float4*)&Qt[d][i0];
            float4 kv = *(const float4*)&KPt[d][j0];
            float qa[4] = {qv.x, qv.y, qv.z, qv.w};
            float ka[4] = {kv.x, kv.y, kv.z, kv.w};
            #pragma unroll
            for (int i = 0; i < 4; i++)
                #pragma unroll
                for (int j = 0; j < 4; j++)
                    s[i][j] += qa[i] * ka[j];
        }
        float bj[4];
        #pragma unroll
        for (int j = 0; j < 4; j++) bj[j] = __ldg(bp + k0 + j0 + j);
        #pragma unroll
        for (int i = 0; i < 4; i++)
            #pragma unroll
            for (int j = 0; j < 4; j++)
                s[i][j] = s[i][j] * 0.125f + bj[j];

        // Online softmax: row stats across the 16-thread (tx) row group
        #pragma unroll
        for (int i = 0; i < 4; i++) {
            float mx = fmaxf(fmaxf(s[i][0], s[i][1]), fmaxf(s[i][2], s[i][3]));
            for (int w = 1; w < 16; w <<= 1)
                mx = fmaxf(mx, __shfl_xor_sync(0xffffffffu, mx, w));
            float newm = fmaxf(m[i], mx);
            float sc   = __expf(m[i] - newm);
            m[i] = newm;

            float su = 0.f;
            #pragma unroll
            for (int j = 0; j < 4; j++) {
                s[i][j] = __expf(s[i][j] - newm);
                su += s[i][j];
            }
            for (int w = 1; w < 16; w <<= 1)
                su += __shfl_xor_sync(0xffffffffu, su, w);
            l[i] = l[i] * sc + su;
            #pragma unroll
            for (int d = 0; d < 4; d++) o[i][d] *= sc;
        }

        __syncthreads();   // all S-stage reads of KPt done before P^T overwrite

        // Write P transposed (swizzled): P[i][j] -> KPt[j][(i + 4*(j>>2)) & 63]
        #pragma unroll
        for (int j = 0; j < 4; j++) {
            int jg  = j0 + j;
            int col = (i0 + ((jg >> 2) << 2)) & 63;
            float4 pv = make_float4(s[0][j], s[1][j], s[2][j], s[3][j]);
            *(float4*)&KPt[jg][col] = pv;
        }
        __syncthreads();

        // O += P @ V  (thread: rows i0..i0+3, d-cols tx*4..+3)
        #pragma unroll
        for (int j = 0; j < 64; j++) {
            int col = (i0 + ((j >> 2) << 2)) & 63;
            float4 pv = *(const float4*)&KPt[j][col];
            float4 vv = *(const float4*)&Vs[j][tx * 4];
            float pa[4] = {pv.x, pv.y, pv.z, pv.w};
            float va[4] = {vv.x, vv.y, vv.z, vv.w};
            #pragma unroll
            for (int i = 0; i < 4; i++)
                #pragma unroll
                for (int d = 0; d < 4; d++)
                    o[i][d] += pa[i] * va[d];
        }
    }

    // Finalize and write [B,N,D]
    #pragma unroll
    for (int i = 0; i < 4; i++) {
        float inv = 1.f / l[i];
        int n = q0 + i0 + i;
        float4 ov = make_float4(o[i][0] * inv, o[i][1] * inv,
                                o[i][2] * inv, o[i][3] * inv);
        *(float4*)&g_attn[(size_t)(b * Nn + n) * Dd + h * HD + tx * 4] = ov;
    }
}

// ---------------------------------------------------------------------------
static const float* ptr_by_size(void* const* d_in, const int* in_sizes,
                                int n_in, int sz)
{
    for (int i = 0; i < n_in; i++)
        if (in_sizes[i] == sz) return (const float*)d_in[i];
    return nullptr;
}

extern "C" void kernel_launch(void* const* d_in, const int* in_sizes, int n_in,
                              void* d_out, int out_size)
{
    // Map inputs robustly by (distinct) element counts.
    const float* x      = ptr_by_size(d_in, in_sizes, n_in, Bb * Nn * Dd);      // 4,194,304
    const float* abias  = ptr_by_size(d_in, in_sizes, n_in, Bb * Nn);           // 4,096
    const float* w_qkv  = ptr_by_size(d_in, in_sizes, n_in, Dd * 3 * Dd);       // 3,145,728
    const float* b_qkv  = ptr_by_size(d_in, in_sizes, n_in, 3 * Dd);            // 3,072
    const float* w_proj = ptr_by_size(d_in, in_sizes, n_in, Dd * Dd);           // 1,048,576
    const float* b_proj = ptr_by_size(d_in, in_sizes, n_in, Dd);                // 1,024
    float* out = (float*)d_out;

    // 1) QKV projection, scattered into attention-friendly layouts
    sgemm_kernel<3 * Dd, 0><<<dim3(24, 32), 256>>>(x, w_qkv, b_qkv, nullptr);

    // 2) Attention (flash-style, online softmax)
    attn_kernel<<<dim3(Nn / 64, Bb * Hh), 256>>>(abias);

    // 3) Output projection
    sgemm_kernel<Dd, 1><<<dim3(8, 32), 256>>>(nullptr, w_proj, b_proj, out);
}

// round 3
// speedup vs baseline: 2.7827x; 2.7827x over previous
#include <cuda_runtime.h>

#define Bb 2
#define Nn 2048
#define Dd 1024
#define Hh 16
#define HD 64

// Scratch (static device arrays -- no allocation allowed)
__device__ float g_q   [Bb*Hh*Nn*HD];   // [bh][n][hd]
__device__ float g_k   [Bb*Hh*Nn*HD];   // [bh][n][hd]
__device__ float g_vt  [Bb*Hh*HD*Nn];   // [bh][hd][n]  (transposed for P@V)
__device__ float g_attn[Bb*Nn*Dd];      // [B*N, D]

// ---------------------------------------------------------------------------
// TF32 helpers (m16n8k8 mma.sync, Ampere-style fragments)
// ---------------------------------------------------------------------------
__device__ __forceinline__ unsigned f2tf(float f) {
    unsigned u; asm("cvt.rna.tf32.f32 %0, %1;" : "=r"(u) : "f"(f)); return u;
}
__device__ __forceinline__ void mma_tf32(float* d, const unsigned* a, const unsigned* b) {
    asm("mma.sync.aligned.m16n8k8.row.col.f32.tf32.tf32.f32 "
        "{%0,%1,%2,%3},{%4,%5,%6,%7},{%8,%9},{%0,%1,%2,%3};"
        : "+f"(d[0]), "+f"(d[1]), "+f"(d[2]), "+f"(d[3])
        : "r"(a[0]), "r"(a[1]), "r"(a[2]), "r"(a[3]), "r"(b[0]), "r"(b[1]));
}

// ---------------------------------------------------------------------------
// TF32 GEMM 128x128x32, 256 threads (8 warps, 2x4), warp tile 64x32.
// EPI==0: C = x @ w_qkv + b, scattered into q/k/vt scratch
// EPI==1: C = g_attn @ w_proj + b -> Cout
// ---------------------------------------------------------------------------
template<int NCOLS, int EPI>
__global__ void __launch_bounds__(256, 2)
gemm_tf32(const float* __restrict__ A, const float* __restrict__ B,
          const float* __restrict__ bias, float* __restrict__ Cout)
{
    __shared__ unsigned As[128][36];   // [m][k], pad 4
    __shared__ unsigned Bs[32][136];   // [k][n], pad 8

    const int t  = threadIdx.x;
    const int w  = t >> 5;
    const int ln = t & 31;
    const int g  = ln >> 2;            // group id (0..7)
    const int c  = ln & 3;             // thread in group
    const int wm = (w >> 2) * 64;      // warp m offset (0/64)
    const int wn = (w & 3) * 32;       // warp n offset
    const int m0 = blockIdx.y * 128;
    const int n0 = blockIdx.x * 128;

    const float* Ap = (EPI == 1) ? g_attn : A;

    float acc[4][4][4];
    #pragma unroll
    for (int mt = 0; mt < 4; mt++)
        #pragma unroll
        for (int nt = 0; nt < 4; nt++)
            #pragma unroll
            for (int i = 0; i < 4; i++) acc[mt][nt][i] = 0.f;

    for (int k0 = 0; k0 < 1024; k0 += 32) {
        // A tile 128x32
        #pragma unroll
        for (int s = 0; s < 4; s++) {
            int idx = t + s * 256;            // 1024 float4 slots
            int row = idx >> 3, col = (idx & 7) * 4;
            float4 v = *(const float4*)(Ap + (size_t)(m0 + row) * 1024 + k0 + col);
            uint4 u = make_uint4(f2tf(v.x), f2tf(v.y), f2tf(v.z), f2tf(v.w));
            *(uint4*)&As[row][col] = u;
        }
        // B tile 32x128
        #pragma unroll
        for (int s = 0; s < 4; s++) {
            int idx = t + s * 256;
            int row = idx >> 5, col = (idx & 31) * 4;
            float4 v = *(const float4*)(B + (size_t)(k0 + row) * NCOLS + n0 + col);
            uint4 u = make_uint4(f2tf(v.x), f2tf(v.y), f2tf(v.z), f2tf(v.w));
            *(uint4*)&Bs[row][col] = u;
        }
        __syncthreads();

        #pragma unroll
        for (int kk = 0; kk < 32; kk += 8) {
            unsigned af[4][4], bf[4][2];
            #pragma unroll
            for (int mt = 0; mt < 4; mt++) {
                int r = wm + mt * 16;
                af[mt][0] = As[r + g    ][kk + c];
                af[mt][1] = As[r + g + 8][kk + c];
                af[mt][2] = As[r + g    ][kk + c + 4];
                af[mt][3] = As[r + g + 8][kk + c + 4];
            }
            #pragma unroll
            for (int nt = 0; nt < 4; nt++) {
                int cc = wn + nt * 8 + g;
                bf[nt][0] = Bs[kk + c    ][cc];
                bf[nt][1] = Bs[kk + c + 4][cc];
            }
            #pragma unroll
            for (int mt = 0; mt < 4; mt++)
                #pragma unroll
                for (int nt = 0; nt < 4; nt++)
                    mma_tf32(acc[mt][nt], af[mt], bf[nt]);
        }
        __syncthreads();
    }

    // Epilogue
    float bv[4][2];
    #pragma unroll
    for (int nt = 0; nt < 4; nt++) {
        int col = n0 + wn + nt * 8 + 2 * c;
        bv[nt][0] = __ldg(bias + col);
        bv[nt][1] = __ldg(bias + col + 1);
    }
    #pragma unroll
    for (int mt = 0; mt < 4; mt++) {
        #pragma unroll
        for (int half = 0; half < 2; half++) {
            int r = m0 + wm + mt * 16 + g + half * 8;
            #pragma unroll
            for (int nt = 0; nt < 4; nt++) {
                int col = n0 + wn + nt * 8 + 2 * c;
                float v0 = acc[mt][nt][half * 2 + 0] + bv[nt][0];
                float v1 = acc[mt][nt][half * 2 + 1] + bv[nt][1];
                if (EPI == 0) {
                    int b = r >> 11, n = r & 2047;
                    #pragma unroll
                    for (int e = 0; e < 2; e++) {
                        int cc = col + e;
                        float v = e ? v1 : v0;
                        int tt = cc >> 10, rem = cc & 1023;
                        int h = rem >> 6, d = rem & 63;
                        int bh = b * Hh + h;
                        if (tt == 0)      g_q [((size_t)(bh * Nn + n) << 6) + d] = v;
                        else if (tt == 1) g_k [((size_t)(bh * Nn + n) << 6) + d] = v;
                        else              g_vt[((size_t)(bh * HD + d) << 11) + n] = v;
                    }
                } else {
                    *(float2*)(Cout + (size_t)r * 1024 + col) = make_float2(v0, v1);
                }
            }
        }
    }
}

// ---------------------------------------------------------------------------
// Flash attention, TF32 tensor cores.
// Block: 128 threads (4 warps), 64-query tile; warp owns 16 query rows.
// Q fragments register-resident. K buffer reused for P staging.
// ---------------------------------------------------------------------------
__global__ void __launch_bounds__(128)
attn_tf32(const float* __restrict__ bias)
{
    __shared__ unsigned KP[64][68];   // K tile [key][d]; reused as P [q][key]
    __shared__ unsigned Vt[64][68];   // V^T tile [d][key]

    const int t  = threadIdx.x;
    const int w  = t >> 5;
    const int ln = t & 31;
    const int g  = ln >> 2;
    const int c  = ln & 3;
    const int wq = w * 16;            // warp's query-row offset in tile
    const int bh = blockIdx.y;
    const int b  = bh >> 4;
    const int h  = bh & 15;
    const int q0 = blockIdx.x * 64;

    const float* qp  = g_q  + ((size_t)bh * Nn) * HD;
    const float* kp  = g_k  + ((size_t)bh * Nn) * HD;
    const float* vtp = g_vt + ((size_t)bh * HD) * Nn;
    const float* bp  = bias + b * Nn;

    // Stage Q tile [64q][64d] through KP, extract register fragments
    #pragma unroll
    for (int s = 0; s < 8; s++) {
        int idx = t + s * 128;                // 1024 float4 slots
        int row = idx >> 4, col = (idx & 15) * 4;
        float4 v = *(const float4*)(qp + (size_t)(q0 + row) * HD + col);
        uint4 u = make_uint4(f2tf(v.x), f2tf(v.y), f2tf(v.z), f2tf(v.w));
        *(uint4*)&KP[row][col] = u;
    }
    __syncthreads();
    unsigned qf[8][4];
    #pragma unroll
    for (int kk = 0; kk < 8; kk++) {
        qf[kk][0] = KP[wq + g    ][kk * 8 + c];
        qf[kk][1] = KP[wq + g + 8][kk * 8 + c];
        qf[kk][2] = KP[wq + g    ][kk * 8 + c + 4];
        qf[kk][3] = KP[wq + g + 8][kk * 8 + c + 4];
    }

    float oacc[8][4];
    #pragma unroll
    for (int dn = 0; dn < 8; dn++)
        #pragma unroll
        for (int i = 0; i < 4; i++) oacc[dn][i] = 0.f;
    float m[2] = {-1e30f, -1e30f};
    float l[2] = {0.f, 0.f};

    for (int k0 = 0; k0 < Nn; k0 += 64) {
        __syncthreads();   // prior reads of KP/Vt complete (incl. Q frags, PV)

        // Load K tile [key][d] and V^T tile [d][key]
        #pragma unroll
        for (int s = 0; s < 8; s++) {
            int idx = t + s * 128;
            int row = idx >> 4, col = (idx & 15) * 4;
            float4 kv = *(const float4*)(kp + (size_t)(k0 + row) * HD + col);
            *(uint4*)&KP[row][col] =
                make_uint4(f2tf(kv.x), f2tf(kv.y), f2tf(kv.z), f2tf(kv.w));
            float4 vv = *(const float4*)(vtp + (size_t)row * Nn + k0 + col);
            *(uint4*)&Vt[row][col] =
                make_uint4(f2tf(vv.x), f2tf(vv.y), f2tf(vv.z), f2tf(vv.w));
        }
        __syncthreads();

        // S = Q @ K^T  (16 rows x 64 keys per warp)
        float sacc[8][4];
        #pragma unroll
        for (int nt = 0; nt < 8; nt++)
            #pragma unroll
            for (int i = 0; i < 4; i++) sacc[nt][i] = 0.f;

        #pragma unroll
        for (int kk = 0; kk < 8; kk++) {
            unsigned bf[8][2];
            #pragma unroll
            for (int nt = 0; nt < 8; nt++) {
                bf[nt][0] = KP[nt * 8 + g][kk * 8 + c];
                bf[nt][1] = KP[nt * 8 + g][kk * 8 + c + 4];
            }
            #pragma unroll
            for (int nt = 0; nt < 8; nt++)
                mma_tf32(sacc[nt], qf[kk], bf[nt]);
        }

        // scale + bias
        #pragma unroll
        for (int nt = 0; nt < 8; nt++) {
            int col = k0 + nt * 8 + 2 * c;
            float b0 = __ldg(bp + col), b1 = __ldg(bp + col + 1);
            sacc[nt][0] = sacc[nt][0] * 0.125f + b0;
            sacc[nt][1] = sacc[nt][1] * 0.125f + b1;
            sacc[nt][2] = sacc[nt][2] * 0.125f + b0;
            sacc[nt][3] = sacc[nt][3] * 0.125f + b1;
        }

        // Online softmax (rows g and g+8; row spread across 4 lanes c=0..3)
        #pragma unroll
        for (int r = 0; r < 2; r++) {
            float mx = -1e30f;
            #pragma unroll
            for (int nt = 0; nt < 8; nt++)
                mx = fmaxf(mx, fmaxf(sacc[nt][2 * r], sacc[nt][2 * r + 1]));
            mx = fmaxf(mx, __shfl_xor_sync(0xffffffffu, mx, 1));
            mx = fmaxf(mx, __shfl_xor_sync(0xffffffffu, mx, 2));
            float mnew = fmaxf(m[r], mx);
            float sc = __expf(m[r] - mnew);
            m[r] = mnew;
            float su = 0.f;
            #pragma unroll
            for (int nt = 0; nt < 8; nt++) {
                float p0 = __expf(sacc[nt][2 * r]     - mnew);
                float p1 = __expf(sacc[nt][2 * r + 1] - mnew);
                sacc[nt][2 * r] = p0; sacc[nt][2 * r + 1] = p1;
                su += p0 + p1;
            }
            su += __shfl_xor_sync(0xffffffffu, su, 1);
            su += __shfl_xor_sync(0xffffffffu, su, 2);
            l[r] = l[r] * sc + su;
            #pragma unroll
            for (int dn = 0; dn < 8; dn++) {
                oacc[dn][2 * r]     *= sc;
                oacc[dn][2 * r + 1] *= sc;
            }
        }

        __syncthreads();   // all warps done reading KP (K)

        // Write P into KP as [q][key]
        #pragma unroll
        for (int nt = 0; nt < 8; nt++) {
            int col = nt * 8 + 2 * c;
            KP[wq + g    ][col    ] = f2tf(sacc[nt][0]);
            KP[wq + g    ][col + 1] = f2tf(sacc[nt][1]);
            KP[wq + g + 8][col    ] = f2tf(sacc[nt][2]);
            KP[wq + g + 8][col + 1] = f2tf(sacc[nt][3]);
        }
        __syncthreads();

        // O += P @ V   (k over 64 keys, n over 64 d)
        #pragma unroll
        for (int kk = 0; kk < 8; kk++) {
            unsigned pa[4];
            pa[0] = KP[wq + g    ][kk * 8 + c];
            pa[1] = KP[wq + g + 8][kk * 8 + c];
            pa[2] = KP[wq + g    ][kk * 8 + c + 4];
            pa[3] = KP[wq + g + 8][kk * 8 + c + 4];
            #pragma unroll
            for (int dn = 0; dn < 8; dn++) {
                unsigned vb[2];
                vb[0] = Vt[dn * 8 + g][kk * 8 + c];
                vb[1] = Vt[dn * 8 + g][kk * 8 + c + 4];
                mma_tf32(oacc[dn], pa, vb);
            }
        }
    }

    // Finalize: O /= l, write [B,N,D]
    float inv[2] = {1.f / l[0], 1.f / l[1]};
    #pragma unroll
    for (int r = 0; r < 2; r++) {
        int n = q0 + wq + g + r * 8;
        float* outp = g_attn + ((size_t)(b * Nn + n)) * Dd + h * HD;
        #pragma unroll
        for (int dn = 0; dn < 8; dn++) {
            int col = dn * 8 + 2 * c;
            *(float2*)(outp + col) = make_float2(oacc[dn][2 * r] * inv[r],
                                                 oacc[dn][2 * r + 1] * inv[r]);
        }
    }
}

// ---------------------------------------------------------------------------
static const float* ptr_by_size(void* const* d_in, const int* in_sizes,
                                int n_in, int sz)
{
    for (int i = 0; i < n_in; i++)
        if (in_sizes[i] == sz) return (const float*)d_in[i];
    return nullptr;
}

extern "C" void kernel_launch(void* const* d_in, const int* in_sizes, int n_in,
                              void* d_out, int out_size)
{
    const float* x      = ptr_by_size(d_in, in_sizes, n_in, Bb * Nn * Dd);
    const float* abias  = ptr_by_size(d_in, in_sizes, n_in, Bb * Nn);
    const float* w_qkv  = ptr_by_size(d_in, in_sizes, n_in, Dd * 3 * Dd);
    const float* b_qkv  = ptr_by_size(d_in, in_sizes, n_in, 3 * Dd);
    const float* w_proj = ptr_by_size(d_in, in_sizes, n_in, Dd * Dd);
    const float* b_proj = ptr_by_size(d_in, in_sizes, n_in, Dd);
    float* out = (float*)d_out;

    // 1) QKV projection (tf32 tensor cores), scattered into q/k/vt
    gemm_tf32<3 * Dd, 0><<<dim3(24, 32), 256>>>(x, w_qkv, b_qkv, nullptr);

    // 2) Flash attention (tf32 tensor cores)
    attn_tf32<<<dim3(Nn / 64, Bb * Hh), 128>>>(abias);

    // 3) Output projection
    gemm_tf32<Dd, 1><<<dim3(8, 32), 256>>>(nullptr, w_proj, b_proj, out);
}